// round 12
// baseline (speedup 1.0000x reference)
#include <cuda_runtime.h>
#include <cuda_fp16.h>
#include <cstdint>

#define BB 16
#define LL 4096
#define DD 512
#define KK 2048
#define NROWS 32768

#define MT 128            // rows per CTA
#define NT 128            // codes per CTA
#define KC 64             // k elems per stage (128B rows)
#define NSTAGE (DD / KC)  // 8
#define NCTQ (KK / NT)    // 16
#define CBSCALE 2048.0f   // codebook scale: argmin-invariant, keeps fp16 in range
#define MARGIN 2.0f       // rescore margin (scaled units), >> worst-case fp16 score err

// ------------------------------------------------------------- device scratch
__device__ float   g_means[NROWS * DD];   // fp32 (exact rescore)
__device__ __half  g_mh[NROWS * DD];      // means (fp16)
__device__ __half  g_ch[KK * DD];         // codebook*2048 (fp16)
__device__ int     g_idx[NROWS];
__device__ float   g_cbsq[KK];
__device__ float   g_s[KK];
__device__ float4  g_part[NROWS * NCTQ];  // per (row, ctile): v1,i1,v2,i2

// ------------------------------------------------------------- PTX helpers
__device__ __forceinline__ uint32_t smem_u32(const void* p) {
    uint32_t a;
    asm("{ .reg .u64 t; cvta.to.shared.u64 t, %1; cvt.u32.u64 %0, t; }" : "=r"(a) : "l"(p));
    return a;
}
#define CP16(dst, src) \
    asm volatile("cp.async.cg.shared.global [%0], [%1], 16;" :: "r"(dst), "l"(src))
#define CP_COMMIT() asm volatile("cp.async.commit_group;" ::: "memory")
#define CP_WAIT1()  asm volatile("cp.async.wait_group 1;" ::: "memory")
#define LDSM_X4(r0, r1, r2, r3, addr)                                             \
    asm volatile("ldmatrix.sync.aligned.m8n8.x4.shared.b16 {%0,%1,%2,%3}, [%4];"  \
        : "=r"(r0), "=r"(r1), "=r"(r2), "=r"(r3) : "r"(addr))
__device__ __forceinline__ void mma_f16(float* d, const uint32_t* a, const uint32_t* b) {
    asm volatile(
        "mma.sync.aligned.m16n8k16.row.col.f32.f16.f16.f32 "
        "{%0,%1,%2,%3}, {%4,%5,%6,%7}, {%8,%9}, {%0,%1,%2,%3};"
        : "+f"(d[0]), "+f"(d[1]), "+f"(d[2]), "+f"(d[3])
        : "r"(a[0]), "r"(a[1]), "r"(a[2]), "r"(a[3]), "r"(b[0]), "r"(b[1]));
}
__device__ __forceinline__ uint32_t pack_h2(__half a, __half b) {
    return (uint32_t)__half_as_ushort(a) | ((uint32_t)__half_as_ushort(b) << 16);
}

// ------------------------------------------------------------- K1: means + fp16
__global__ void means_kernel(const float4* __restrict__ E) {
    int i = blockIdx.x * blockDim.x + threadIdx.x;
    const int D4 = DD / 4;
    if (i >= NROWS * D4) return;
    int row = i / D4, d4 = i - row * D4;
    float4 a = E[(2 * row) * D4 + d4];
    float4 b = E[(2 * row + 1) * D4 + d4];
    float4 m;
    m.x = 0.5f * (a.x + b.x); m.y = 0.5f * (a.y + b.y);
    m.z = 0.5f * (a.z + b.z); m.w = 0.5f * (a.w + b.w);
    ((float4*)g_means)[i] = m;
    ((uint2*)g_mh)[i] = make_uint2(
        pack_h2(__float2half_rn(m.x), __float2half_rn(m.y)),
        pack_h2(__float2half_rn(m.z), __float2half_rn(m.w)));
}

// ------------------------------------------------------------- K1b: codebook scale -> fp16
__global__ void cbsplit_kernel(const float4* __restrict__ Cb4) {
    int i = blockIdx.x * blockDim.x + threadIdx.x;
    if (i >= KK * DD / 4) return;
    float4 m = Cb4[i];
    ((uint2*)g_ch)[i] = make_uint2(
        pack_h2(__float2half_rn(m.x * CBSCALE), __float2half_rn(m.y * CBSCALE)),
        pack_h2(__float2half_rn(m.z * CBSCALE), __float2half_rn(m.w * CBSCALE)));
}

// ------------------------------------------------------------- K2: prep (cbsq + per-code loss)
__global__ __launch_bounds__(256) void prep_kernel(const float* __restrict__ Cb,
                                                   const float* __restrict__ W,
                                                   const float* __restrict__ bias) {
    __shared__ float Ck[8][DD];
    __shared__ float sred[8][8];
    int tid = threadIdx.x, warp = tid >> 5, lane = tid & 31;
    int k0 = blockIdx.x * 8;
    for (int i = tid; i < 8 * DD; i += 256) {
        int kk = i / DD, d = i - kk * DD;
        Ck[kk][d] = Cb[(k0 + kk) * DD + d];
    }
    __syncthreads();
    {
        float sq = 0.f;
        for (int d = lane; d < DD; d += 32) { float v = Ck[warp][d]; sq = fmaf(v, v, sq); }
        #pragma unroll
        for (int o = 16; o; o >>= 1) sq += __shfl_xor_sync(0xffffffffu, sq, o);
        if (lane == 0) g_cbsq[k0 + warp] = sq;
    }
    float sacc[8];
    #pragma unroll
    for (int kk = 0; kk < 8; kk++) sacc[kk] = 0.f;
    for (int e = warp; e < DD; e += 8) {
        float p[8];
        #pragma unroll
        for (int kk = 0; kk < 8; kk++) p[kk] = 0.f;
        for (int d = lane; d < DD; d += 32) {
            float wv = W[e * DD + d];
            #pragma unroll
            for (int kk = 0; kk < 8; kk++) p[kk] = fmaf(Ck[kk][d], wv, p[kk]);
        }
        #pragma unroll
        for (int kk = 0; kk < 8; kk++) {
            #pragma unroll
            for (int o = 16; o; o >>= 1) p[kk] += __shfl_xor_sync(0xffffffffu, p[kk], o);
        }
        if (lane == 0) {
            float be = bias[e];
            #pragma unroll
            for (int kk = 0; kk < 8; kk++) {
                float diff = p[kk] + be - Ck[kk][e];
                sacc[kk] = fmaf(diff, diff, sacc[kk]);
            }
        }
    }
    if (lane == 0) {
        #pragma unroll
        for (int kk = 0; kk < 8; kk++) sred[warp][kk] = sacc[kk];
    }
    __syncthreads();
    if (tid < 8) {
        float s = 0.f;
        #pragma unroll
        for (int w = 0; w < 8; w++) s += sred[w][tid];
        g_s[k0 + tid] = s;
    }
}

// ------------------------------------------------------------- K3: single-pass fp16 GEMM + top-2
// CTA tile 128x128, 256 threads, 8 warps (2 row x 4 col), warp tile 64x32.
// 2 CTAs/SM (launch_bounds(256,2)) so one CTA's barriers hide under the other's MMAs.
// Rows: 128B = 64 fp16 of one k-stage, 16B chunks XOR-swizzled by row&7.
// smem: A0[0,16K) A1[16K,32K) B0[32K,48K) B1[48K,64K) cbs@65536. red aliases A0.
#define SMEM_GEMM 66048

__global__ __launch_bounds__(256, 2) void gemm_argmin() {
    extern __shared__ char smraw[];
    uint32_t sb = smem_u32(smraw);
    int tid = threadIdx.x;
    int lane = tid & 31, wid = tid >> 5;
    int wm = wid >> 2, wn = wid & 3;        // warp tile: rows wm*64, cols wn*32
    int row0 = blockIdx.x * MT;
    int ctbase = blockIdx.y * NT;

    const uint32_t smA[2] = { sb, sb + 16384 };
    const uint32_t smB[2] = { sb + 32768, sb + 49152 };
    float* cbs = (float*)(smraw + 65536);
    float4* red = (float4*)smraw;           // alias: used only after mainloop (8KB < 16KB)

    if (tid < NT) cbs[tid] = g_cbsq[ctbase + tid] * CBSCALE;

    // ldmatrix lane-invariants
    const int rA = lane & 15, cA = lane >> 4;        // A: rows 0-15, 16B half of k16
    const int rB = (lane & 7) | ((lane >> 4) << 3);  // B: n row within 16
    const int cB = (lane >> 3) & 1;                  // B: 16B half of k16

    float acc[4][4][4];
    #pragma unroll
    for (int a = 0; a < 4; a++)
        #pragma unroll
        for (int b = 0; b < 4; b++)
            #pragma unroll
            for (int c = 0; c < 4; c++) acc[a][b][c] = 0.f;

    // loaders: row tid>>1 (0..127), chunk group (tid&1)*4; A and B identically
    const int ldrow = tid >> 1, ld4 = (tid & 1) * 4;

    auto issue = [&](int s, int b) {
        uint32_t x = (uint32_t)(ldrow & 7);
        {
            const __half* p = g_mh + (size_t)(row0 + ldrow) * DD + s * KC + ld4 * 8;
            uint32_t base = smA[b] + ldrow * 128;
            #pragma unroll
            for (int c = 0; c < 4; c++)
                CP16(base + ((((uint32_t)(ld4 + c)) ^ x) << 4), p + 8 * c);
        }
        {
            const __half* p = g_ch + (size_t)(ctbase + ldrow) * DD + s * KC + ld4 * 8;
            uint32_t base = smB[b] + ldrow * 128;
            #pragma unroll
            for (int c = 0; c < 4; c++)
                CP16(base + ((((uint32_t)(ld4 + c)) ^ x) << 4), p + 8 * c);
        }
    };

    issue(0, 0); CP_COMMIT();
    issue(1, 1); CP_COMMIT();

    for (int s = 0; s < NSTAGE; s++) {
        const int b = s & 1;
        CP_WAIT1();
        __syncthreads();

        #pragma unroll
        for (int kk = 0; kk < 4; kk++) {
            uint32_t ah[4][4], bh[4][2];
            #pragma unroll
            for (int mf = 0; mf < 4; mf++) {
                int row = wm * 64 + mf * 16 + rA;
                uint32_t ba = smA[b] + row * 128;
                uint32_t x = (uint32_t)(row & 7);
                LDSM_X4(ah[mf][0], ah[mf][1], ah[mf][2], ah[mf][3],
                        ba + ((((uint32_t)(2 * kk + cA)) ^ x) << 4));
            }
            #pragma unroll
            for (int np = 0; np < 2; np++) {
                int n = wn * 32 + np * 16 + rB;
                uint32_t bb = smB[b] + n * 128;
                uint32_t x = (uint32_t)(n & 7);
                uint32_t t0, t1, t2, t3;
                LDSM_X4(t0, t1, t2, t3, bb + ((((uint32_t)(2 * kk + cB)) ^ x) << 4));
                bh[2 * np][0] = t0; bh[2 * np][1] = t1;
                bh[2 * np + 1][0] = t2; bh[2 * np + 1][1] = t3;
            }
            #pragma unroll
            for (int mf = 0; mf < 4; mf++)
                #pragma unroll
                for (int nf = 0; nf < 4; nf++)
                    mma_f16(acc[mf][nf], ah[mf], bh[nf]);
        }
        __syncthreads();
        if (s + 2 < NSTAGE) issue(s + 2, b);
        CP_COMMIT();
    }
    __syncthreads();   // before aliasing smA as red[]

    // ---- epilogue: scores + per-row top-2 ----
    int g = lane >> 2, q = lane & 3;
    #pragma unroll
    for (int mf = 0; mf < 4; mf++) {
        #pragma unroll
        for (int half = 0; half < 2; half++) {
            int rloc = wm * 64 + mf * 16 + half * 8 + g;
            float v1 = 3.4e38f, v2 = 3.4e38f;
            int i1 = 0, i2 = 0;
            #pragma unroll
            for (int nf = 0; nf < 4; nf++) {
                #pragma unroll
                for (int j = 0; j < 2; j++) {
                    int cloc = wn * 32 + nf * 8 + 2 * q + j;
                    float sc = fmaf(-2.0f, acc[mf][nf][half * 2 + j], cbs[cloc]);
                    int code = ctbase + cloc;
                    if (sc < v1) { v2 = v1; i2 = i1; v1 = sc; i1 = code; }
                    else if (sc < v2) { v2 = sc; i2 = code; }
                }
            }
            #pragma unroll
            for (int o = 1; o <= 2; o <<= 1) {
                float w1 = __shfl_xor_sync(0xffffffffu, v1, o);
                int   j1 = __shfl_xor_sync(0xffffffffu, i1, o);
                float w2 = __shfl_xor_sync(0xffffffffu, v2, o);
                int   j2 = __shfl_xor_sync(0xffffffffu, i2, o);
                if (w1 < v1 || (w1 == v1 && j1 < i1)) { v2 = v1; i2 = i1; v1 = w1; i1 = j1; }
                else if (w1 < v2 || (w1 == v2 && j1 < i2)) { v2 = w1; i2 = j1; }
                if (w2 < v1 || (w2 == v1 && j2 < i1)) { v2 = v1; i2 = i1; v1 = w2; i1 = j2; }
                else if (w2 < v2 || (w2 == v2 && j2 < i2)) { v2 = w2; i2 = j2; }
            }
            if (q == 0)
                red[rloc * 4 + wn] =
                    make_float4(v1, __int_as_float(i1), v2, __int_as_float(i2));
        }
    }
    __syncthreads();
    if (tid < MT) {
        float v1 = 3.4e38f, v2 = 3.4e38f;
        int i1 = 0x7fffffff, i2 = 0x7fffffff;
        #pragma unroll
        for (int w = 0; w < 4; w++) {
            float4 p = red[tid * 4 + w];
            float w1 = p.x, w2 = p.z;
            int j1 = __float_as_int(p.y), j2 = __float_as_int(p.w);
            if (w1 < v1 || (w1 == v1 && j1 < i1)) { v2 = v1; i2 = i1; v1 = w1; i1 = j1; }
            else if (w1 < v2 || (w1 == v2 && j1 < i2)) { v2 = w1; i2 = j1; }
            if (w2 < v1 || (w2 == v1 && j2 < i1)) { v2 = v1; i2 = i1; v1 = w2; i1 = j2; }
            else if (w2 < v2 || (w2 == v2 && j2 < i2)) { v2 = w2; i2 = j2; }
        }
        g_part[(size_t)(row0 + tid) * NCTQ + blockIdx.y] =
            make_float4(v1, __int_as_float(i1), v2, __int_as_float(i2));
    }
}

// ------------------------------------------------------------- K4: margin-pruned exact rescore
// Warp per row: 32 candidates (top-2 x 16 tiles); exact-rescore only those within
// MARGIN of the fp16 min, warp-cooperatively (coalesced). Then argmin + gather.
__global__ __launch_bounds__(256) void combine_kernel(const float* __restrict__ Cb,
                                                      float* __restrict__ out_idx_f,
                                                      float4* __restrict__ out_emb4) {
    int row = blockIdx.x * 8 + (threadIdx.x >> 5);
    int lane = threadIdx.x & 31;

    float4 p = g_part[(size_t)row * NCTQ + (lane & 15)];
    float v  = (lane < 16) ? p.x : p.z;
    int   ci = (lane < 16) ? __float_as_int(p.y) : __float_as_int(p.w);

    float vmin = v;
    #pragma unroll
    for (int o = 16; o; o >>= 1) vmin = fminf(vmin, __shfl_xor_sync(0xffffffffu, vmin, o));

    unsigned mask = __ballot_sync(0xffffffffu, v <= vmin + MARGIN);

    const float4* m4 = (const float4*)&g_means[(size_t)row * DD];
    float bv = 3.4e38f;
    int bi = 0x7fffffff;
    while (mask) {
        int src = __ffs(mask) - 1;
        mask &= mask - 1;
        int cand = __shfl_sync(0xffffffffu, ci, src);
        const float4* c4 = (const float4*)&Cb[(size_t)cand * DD];
        float a0 = 0.f, a1 = 0.f, a2 = 0.f, a3 = 0.f;
        #pragma unroll
        for (int j = 0; j < 4; j++) {
            float4 mv = m4[lane + 32 * j];
            float4 cv = c4[lane + 32 * j];
            a0 = fmaf(mv.x, cv.x, a0);
            a1 = fmaf(mv.y, cv.y, a1);
            a2 = fmaf(mv.z, cv.z, a2);
            a3 = fmaf(mv.w, cv.w, a3);
        }
        float dot = (a0 + a1) + (a2 + a3);
        #pragma unroll
        for (int o = 16; o; o >>= 1) dot += __shfl_xor_sync(0xffffffffu, dot, o);
        float sv = fmaf(-2.f, dot, g_cbsq[cand]);
        if (sv < bv || (sv == bv && cand < bi)) { bv = sv; bi = cand; }
    }
    if (lane == 0) {
        g_idx[row] = bi;
        out_idx_f[row] = (float)bi;
    }
    // fused gather (coalesced, codebook L2-hot)
    const float4* src4 = (const float4*)&Cb[(size_t)bi * DD];
    float4* dst = out_emb4 + (size_t)row * (DD / 4);
    #pragma unroll
    for (int j = 0; j < 4; j++)
        dst[lane + 32 * j] = src4[lane + 32 * j];
}

// ------------------------------------------------------------- K5: loss
__global__ void loss_kernel(float* __restrict__ out_loss) {
    __shared__ float red[1024];
    float s = 0.f;
    for (int n = threadIdx.x; n < NROWS; n += 1024) s += g_s[g_idx[n]];
    red[threadIdx.x] = s;
    __syncthreads();
    for (int st = 512; st > 0; st >>= 1) {
        if (threadIdx.x < st) red[threadIdx.x] += red[threadIdx.x + st];
        __syncthreads();
    }
    if (threadIdx.x == 0)
        out_loss[0] = red[0] / (float)((long long)NROWS * DD);
}

// -------------------------------------------------------------
extern "C" void kernel_launch(void* const* d_in, const int* in_sizes, int n_in,
                              void* d_out, int out_size) {
    const float* E    = (const float*)d_in[1];
    const float* Cb   = (const float*)d_in[2];
    const float* W    = (const float*)d_in[3];
    const float* bias = (const float*)d_in[4];

    float* out      = (float*)d_out;
    float* out_idx  = out;
    float* out_emb  = out + NROWS;
    float* out_loss = out + NROWS + NROWS * DD;

    cudaFuncSetAttribute(gemm_argmin, cudaFuncAttributeMaxDynamicSharedMemorySize, SMEM_GEMM);

    means_kernel<<<(NROWS * (DD / 4) + 255) / 256, 256>>>((const float4*)E);
    cbsplit_kernel<<<(KK * DD / 4 + 255) / 256, 256>>>((const float4*)Cb);
    prep_kernel<<<KK / 8, 256>>>(Cb, W, bias);
    gemm_argmin<<<dim3(NROWS / MT, NCTQ), 256, SMEM_GEMM>>>();
    combine_kernel<<<NROWS / 8, 256>>>(Cb, out_idx, (float4*)out_emb);
    loss_kernel<<<1, 1024>>>(out_loss);
}

// round 13
// speedup vs baseline: 1.3638x; 1.3638x over previous
#include <cuda_runtime.h>
#include <cuda_fp16.h>
#include <cstdint>

#define BB 16
#define LL 4096
#define DD 512
#define KK 2048
#define NROWS 32768

#define MT 256            // rows per CTA
#define NT 128            // codes per CTA
#define KC 64             // k elems per stage (128B rows)
#define NSTAGE (DD / KC)  // 8
#define NCTQ (KK / NT)    // 16
#define CBSCALE 2048.0f   // codebook scale: argmin-invariant, keeps fp16 in range
#define MARGIN 2.0f       // rescore margin (scaled units), >> worst-case fp16 score err

// ------------------------------------------------------------- device scratch
__device__ float   g_means[NROWS * DD];   // fp32 (exact rescore)
__device__ __half  g_mh[NROWS * DD];      // means (fp16)
__device__ __half  g_ch[KK * DD];         // codebook*2048 (fp16)
__device__ int     g_idx[NROWS];
__device__ float   g_cbsq[KK];
__device__ float   g_s[KK];
__device__ float4  g_part[NROWS * NCTQ];  // per (row, ctile): v1,i1,v2,i2

// ------------------------------------------------------------- PTX helpers
__device__ __forceinline__ uint32_t smem_u32(const void* p) {
    uint32_t a;
    asm("{ .reg .u64 t; cvta.to.shared.u64 t, %1; cvt.u32.u64 %0, t; }" : "=r"(a) : "l"(p));
    return a;
}
#define CP16(dst, src) \
    asm volatile("cp.async.cg.shared.global [%0], [%1], 16;" :: "r"(dst), "l"(src))
#define CP_COMMIT() asm volatile("cp.async.commit_group;" ::: "memory")
#define CP_WAIT2()  asm volatile("cp.async.wait_group 2;" ::: "memory")
#define LDSM_X4(r0, r1, r2, r3, addr)                                             \
    asm volatile("ldmatrix.sync.aligned.m8n8.x4.shared.b16 {%0,%1,%2,%3}, [%4];"  \
        : "=r"(r0), "=r"(r1), "=r"(r2), "=r"(r3) : "r"(addr))
__device__ __forceinline__ void mma_f16(float* d, const uint32_t* a, const uint32_t* b) {
    asm volatile(
        "mma.sync.aligned.m16n8k16.row.col.f32.f16.f16.f32 "
        "{%0,%1,%2,%3}, {%4,%5,%6,%7}, {%8,%9}, {%0,%1,%2,%3};"
        : "+f"(d[0]), "+f"(d[1]), "+f"(d[2]), "+f"(d[3])
        : "r"(a[0]), "r"(a[1]), "r"(a[2]), "r"(a[3]), "r"(b[0]), "r"(b[1]));
}
__device__ __forceinline__ uint32_t pack_h2(__half a, __half b) {
    return (uint32_t)__half_as_ushort(a) | ((uint32_t)__half_as_ushort(b) << 16);
}

// ------------------------------------------------------------- K1: means + fp16
__global__ void means_kernel(const float4* __restrict__ E) {
    int i = blockIdx.x * blockDim.x + threadIdx.x;
    const int D4 = DD / 4;
    if (i >= NROWS * D4) return;
    int row = i / D4, d4 = i - row * D4;
    float4 a = E[(2 * row) * D4 + d4];
    float4 b = E[(2 * row + 1) * D4 + d4];
    float4 m;
    m.x = 0.5f * (a.x + b.x); m.y = 0.5f * (a.y + b.y);
    m.z = 0.5f * (a.z + b.z); m.w = 0.5f * (a.w + b.w);
    ((float4*)g_means)[i] = m;
    ((uint2*)g_mh)[i] = make_uint2(
        pack_h2(__float2half_rn(m.x), __float2half_rn(m.y)),
        pack_h2(__float2half_rn(m.z), __float2half_rn(m.w)));
}

// ------------------------------------------------------------- K2: prep (cbsq + fp16 cb + loss s[k])
__global__ __launch_bounds__(256) void prep_kernel(const float* __restrict__ Cb,
                                                   const float* __restrict__ W,
                                                   const float* __restrict__ bias) {
    __shared__ float Ck[8][DD];
    __shared__ float sred[8][8];
    int tid = threadIdx.x, warp = tid >> 5, lane = tid & 31;
    int k0 = blockIdx.x * 8;
    for (int i = tid; i < 8 * DD; i += 256) {
        int kk = i / DD, d = i - kk * DD;
        float v = Cb[(k0 + kk) * DD + d];
        Ck[kk][d] = v;
        g_ch[(size_t)(k0 + kk) * DD + d] = __float2half_rn(v * CBSCALE);  // folded cbsplit
    }
    __syncthreads();
    {
        float sq = 0.f;
        for (int d = lane; d < DD; d += 32) { float v = Ck[warp][d]; sq = fmaf(v, v, sq); }
        #pragma unroll
        for (int o = 16; o; o >>= 1) sq += __shfl_xor_sync(0xffffffffu, sq, o);
        if (lane == 0) g_cbsq[k0 + warp] = sq;
    }
    float sacc[8];
    #pragma unroll
    for (int kk = 0; kk < 8; kk++) sacc[kk] = 0.f;
    for (int e = warp; e < DD; e += 8) {
        float p[8];
        #pragma unroll
        for (int kk = 0; kk < 8; kk++) p[kk] = 0.f;
        for (int d = lane; d < DD; d += 32) {
            float wv = W[e * DD + d];
            #pragma unroll
            for (int kk = 0; kk < 8; kk++) p[kk] = fmaf(Ck[kk][d], wv, p[kk]);
        }
        #pragma unroll
        for (int kk = 0; kk < 8; kk++) {
            #pragma unroll
            for (int o = 16; o; o >>= 1) p[kk] += __shfl_xor_sync(0xffffffffu, p[kk], o);
        }
        if (lane == 0) {
            float be = bias[e];
            #pragma unroll
            for (int kk = 0; kk < 8; kk++) {
                float diff = p[kk] + be - Ck[kk][e];
                sacc[kk] = fmaf(diff, diff, sacc[kk]);
            }
        }
    }
    if (lane == 0) {
        #pragma unroll
        for (int kk = 0; kk < 8; kk++) sred[warp][kk] = sacc[kk];
    }
    __syncthreads();
    if (tid < 8) {
        float s = 0.f;
        #pragma unroll
        for (int w = 0; w < 8; w++) s += sred[w][tid];
        g_s[k0 + tid] = s;
    }
}

// ------------------------------------------------------------- K3: single-pass fp16 GEMM + top-2
// CTA tile 256x128, 512 threads, 16 warps (4x4), warp tile 64x32, 1 CTA/SM.
// 4-buffer circular cp.async pipeline, ONE __syncthreads per stage, prefetch 3 ahead.
// Rows: 128B = 64 fp16 of one k-stage, 16B chunks XOR-swizzled by row&7.
// smem: A[4x32K @0) B[4x16K @131072) cbs@196608. red aliases A0.
#define SMEM_GEMM 197120

__global__ __launch_bounds__(512, 1) void gemm_argmin() {
    extern __shared__ char smraw[];
    uint32_t sb = smem_u32(smraw);
    int tid = threadIdx.x;
    int lane = tid & 31, wid = tid >> 5;
    int wm = wid >> 2, wn = wid & 3;        // warp tile: rows wm*64, cols wn*32
    int row0 = blockIdx.x * MT;
    int ctbase = blockIdx.y * NT;

    uint32_t smA[4], smB[4];
    #pragma unroll
    for (int b = 0; b < 4; b++) {
        smA[b] = sb + b * 32768;
        smB[b] = sb + 131072 + b * 16384;
    }
    float* cbs = (float*)(smraw + 196608);
    float4* red = (float4*)smraw;           // alias: used only after mainloop (16KB < 32KB)

    if (tid < NT) cbs[tid] = g_cbsq[ctbase + tid] * CBSCALE;

    // ldmatrix lane-invariants
    const int rA = lane & 15, cA = lane >> 4;        // A: rows 0-15, 16B half of k16
    const int rB = (lane & 7) | ((lane >> 4) << 3);  // B: n row within 16
    const int cB = (lane >> 3) & 1;                  // B: 16B half of k16

    float acc[4][4][4];
    #pragma unroll
    for (int a = 0; a < 4; a++)
        #pragma unroll
        for (int b = 0; b < 4; b++)
            #pragma unroll
            for (int c = 0; c < 4; c++) acc[a][b][c] = 0.f;

    // loaders: A row tid>>1 (0..255), chunk group (tid&1)*4; B row tid>>2, pair (tid&3)*2
    const int arow = tid >> 1, ah4 = (tid & 1) * 4;
    const int brow = tid >> 2, bc2 = (tid & 3) * 2;

    auto issue = [&](int s, int b) {
        {
            uint32_t x = (uint32_t)(arow & 7);
            const __half* p = g_mh + (size_t)(row0 + arow) * DD + s * KC + ah4 * 8;
            uint32_t base = smA[b] + arow * 128;
            #pragma unroll
            for (int c = 0; c < 4; c++)
                CP16(base + ((((uint32_t)(ah4 + c)) ^ x) << 4), p + 8 * c);
        }
        {
            uint32_t x = (uint32_t)(brow & 7);
            const __half* p = g_ch + (size_t)(ctbase + brow) * DD + s * KC + bc2 * 8;
            uint32_t base = smB[b] + brow * 128;
            CP16(base + ((((uint32_t)bc2) ^ x) << 4), p);
            CP16(base + ((((uint32_t)(bc2 + 1)) ^ x) << 4), p + 8);
        }
    };

    issue(0, 0); CP_COMMIT();
    issue(1, 1); CP_COMMIT();
    issue(2, 2); CP_COMMIT();

    for (int s = 0; s < NSTAGE; s++) {
        const int b = s & 3;
        CP_WAIT2();             // group s complete (commits so far = s+3)
        __syncthreads();        // all warps done reading buf (s-1)&3 == (s+3)&3
        if (s + 3 < NSTAGE) issue(s + 3, (s + 3) & 3);
        CP_COMMIT();

        #pragma unroll
        for (int kk = 0; kk < 4; kk++) {
            uint32_t ah[4][4], bh[4][2];
            #pragma unroll
            for (int mf = 0; mf < 4; mf++) {
                int row = wm * 64 + mf * 16 + rA;
                uint32_t ba = smA[b] + row * 128;
                uint32_t x = (uint32_t)(row & 7);
                LDSM_X4(ah[mf][0], ah[mf][1], ah[mf][2], ah[mf][3],
                        ba + ((((uint32_t)(2 * kk + cA)) ^ x) << 4));
            }
            #pragma unroll
            for (int np = 0; np < 2; np++) {
                int n = wn * 32 + np * 16 + rB;
                uint32_t bb = smB[b] + n * 128;
                uint32_t x = (uint32_t)(n & 7);
                uint32_t t0, t1, t2, t3;
                LDSM_X4(t0, t1, t2, t3, bb + ((((uint32_t)(2 * kk + cB)) ^ x) << 4));
                bh[2 * np][0] = t0; bh[2 * np][1] = t1;
                bh[2 * np + 1][0] = t2; bh[2 * np + 1][1] = t3;
            }
            #pragma unroll
            for (int mf = 0; mf < 4; mf++)
                #pragma unroll
                for (int nf = 0; nf < 4; nf++)
                    mma_f16(acc[mf][nf], ah[mf], bh[nf]);
        }
    }
    __syncthreads();   // before aliasing smA as red[]

    // ---- epilogue: scores + per-row top-2 ----
    int g = lane >> 2, q = lane & 3;
    #pragma unroll
    for (int mf = 0; mf < 4; mf++) {
        #pragma unroll
        for (int half = 0; half < 2; half++) {
            int rloc = wm * 64 + mf * 16 + half * 8 + g;
            float v1 = 3.4e38f, v2 = 3.4e38f;
            int i1 = 0, i2 = 0;
            #pragma unroll
            for (int nf = 0; nf < 4; nf++) {
                #pragma unroll
                for (int j = 0; j < 2; j++) {
                    int cloc = wn * 32 + nf * 8 + 2 * q + j;
                    float sc = fmaf(-2.0f, acc[mf][nf][half * 2 + j], cbs[cloc]);
                    int code = ctbase + cloc;
                    if (sc < v1) { v2 = v1; i2 = i1; v1 = sc; i1 = code; }
                    else if (sc < v2) { v2 = sc; i2 = code; }
                }
            }
            #pragma unroll
            for (int o = 1; o <= 2; o <<= 1) {
                float w1 = __shfl_xor_sync(0xffffffffu, v1, o);
                int   j1 = __shfl_xor_sync(0xffffffffu, i1, o);
                float w2 = __shfl_xor_sync(0xffffffffu, v2, o);
                int   j2 = __shfl_xor_sync(0xffffffffu, i2, o);
                if (w1 < v1 || (w1 == v1 && j1 < i1)) { v2 = v1; i2 = i1; v1 = w1; i1 = j1; }
                else if (w1 < v2 || (w1 == v2 && j1 < i2)) { v2 = w1; i2 = j1; }
                if (w2 < v1 || (w2 == v1 && j2 < i1)) { v2 = v1; i2 = i1; v1 = w2; i1 = j2; }
                else if (w2 < v2 || (w2 == v2 && j2 < i2)) { v2 = w2; i2 = j2; }
            }
            if (q == 0)
                red[rloc * 4 + wn] =
                    make_float4(v1, __int_as_float(i1), v2, __int_as_float(i2));
        }
    }
    __syncthreads();
    if (tid < MT) {
        float v1 = 3.4e38f, v2 = 3.4e38f;
        int i1 = 0x7fffffff, i2 = 0x7fffffff;
        #pragma unroll
        for (int w = 0; w < 4; w++) {
            float4 p = red[tid * 4 + w];
            float w1 = p.x, w2 = p.z;
            int j1 = __float_as_int(p.y), j2 = __float_as_int(p.w);
            if (w1 < v1 || (w1 == v1 && j1 < i1)) { v2 = v1; i2 = i1; v1 = w1; i1 = j1; }
            else if (w1 < v2 || (w1 == v2 && j1 < i2)) { v2 = w1; i2 = j1; }
            if (w2 < v1 || (w2 == v1 && j2 < i1)) { v2 = v1; i2 = i1; v1 = w2; i1 = j2; }
            else if (w2 < v2 || (w2 == v2 && j2 < i2)) { v2 = w2; i2 = j2; }
        }
        g_part[(size_t)(row0 + tid) * NCTQ + blockIdx.y] =
            make_float4(v1, __int_as_float(i1), v2, __int_as_float(i2));
    }
}

// ------------------------------------------------------------- K4: margin-pruned exact rescore
__global__ __launch_bounds__(256) void combine_kernel(const float* __restrict__ Cb,
                                                      float* __restrict__ out_idx_f,
                                                      float4* __restrict__ out_emb4) {
    int row = blockIdx.x * 8 + (threadIdx.x >> 5);
    int lane = threadIdx.x & 31;

    float4 p = g_part[(size_t)row * NCTQ + (lane & 15)];
    float v  = (lane < 16) ? p.x : p.z;
    int   ci = (lane < 16) ? __float_as_int(p.y) : __float_as_int(p.w);

    float vmin = v;
    #pragma unroll
    for (int o = 16; o; o >>= 1) vmin = fminf(vmin, __shfl_xor_sync(0xffffffffu, vmin, o));

    unsigned mask = __ballot_sync(0xffffffffu, v <= vmin + MARGIN);

    const float4* m4 = (const float4*)&g_means[(size_t)row * DD];
    float bv = 3.4e38f;
    int bi = 0x7fffffff;
    while (mask) {
        int src = __ffs(mask) - 1;
        mask &= mask - 1;
        int cand = __shfl_sync(0xffffffffu, ci, src);
        const float4* c4 = (const float4*)&Cb[(size_t)cand * DD];
        float a0 = 0.f, a1 = 0.f, a2 = 0.f, a3 = 0.f;
        #pragma unroll
        for (int j = 0; j < 4; j++) {
            float4 mv = m4[lane + 32 * j];
            float4 cv = c4[lane + 32 * j];
            a0 = fmaf(mv.x, cv.x, a0);
            a1 = fmaf(mv.y, cv.y, a1);
            a2 = fmaf(mv.z, cv.z, a2);
            a3 = fmaf(mv.w, cv.w, a3);
        }
        float dot = (a0 + a1) + (a2 + a3);
        #pragma unroll
        for (int o = 16; o; o >>= 1) dot += __shfl_xor_sync(0xffffffffu, dot, o);
        float sv = fmaf(-2.f, dot, g_cbsq[cand]);
        if (sv < bv || (sv == bv && cand < bi)) { bv = sv; bi = cand; }
    }
    if (lane == 0) {
        g_idx[row] = bi;
        out_idx_f[row] = (float)bi;
    }
    const float4* src4 = (const float4*)&Cb[(size_t)bi * DD];
    float4* dst = out_emb4 + (size_t)row * (DD / 4);
    #pragma unroll
    for (int j = 0; j < 4; j++)
        dst[lane + 32 * j] = src4[lane + 32 * j];
}

// ------------------------------------------------------------- K5: loss
__global__ void loss_kernel(float* __restrict__ out_loss) {
    __shared__ float red[1024];
    float s = 0.f;
    for (int n = threadIdx.x; n < NROWS; n += 1024) s += g_s[g_idx[n]];
    red[threadIdx.x] = s;
    __syncthreads();
    for (int st = 512; st > 0; st >>= 1) {
        if (threadIdx.x < st) red[threadIdx.x] += red[threadIdx.x + st];
        __syncthreads();
    }
    if (threadIdx.x == 0)
        out_loss[0] = red[0] / (float)((long long)NROWS * DD);
}

// -------------------------------------------------------------
extern "C" void kernel_launch(void* const* d_in, const int* in_sizes, int n_in,
                              void* d_out, int out_size) {
    const float* E    = (const float*)d_in[1];
    const float* Cb   = (const float*)d_in[2];
    const float* W    = (const float*)d_in[3];
    const float* bias = (const float*)d_in[4];

    float* out      = (float*)d_out;
    float* out_idx  = out;
    float* out_emb  = out + NROWS;
    float* out_loss = out + NROWS + NROWS * DD;

    cudaFuncSetAttribute(gemm_argmin, cudaFuncAttributeMaxDynamicSharedMemorySize, SMEM_GEMM);

    means_kernel<<<(NROWS * (DD / 4) + 255) / 256, 256>>>((const float4*)E);
    prep_kernel<<<KK / 8, 256>>>(Cb, W, bias);
    gemm_argmin<<<dim3(NROWS / MT, NCTQ), 512, SMEM_GEMM>>>();
    combine_kernel<<<NROWS / 8, 256>>>(Cb, out_idx, (float4*)out_emb);
    loss_kernel<<<1, 1024>>>(out_loss);
}

// round 14
// speedup vs baseline: 1.4680x; 1.0764x over previous
#include <cuda_runtime.h>
#include <cuda_fp16.h>
#include <cstdint>

#define BB 16
#define LL 4096
#define DD 512
#define KK 2048
#define NROWS 32768

#define MT 256            // rows per CTA
#define NT 128            // codes per CTA
#define KC 64             // k elems per stage (128B rows)
#define NSTAGE (DD / KC)  // 8
#define NCTQ (KK / NT)    // 16
#define CBSCALE 2048.0f   // codebook scale: argmin-invariant, keeps fp16 in range
#define MARGIN 3.0f       // rescore margin (scaled units) >> fp16+f16acc score err (~0.2)

// ------------------------------------------------------------- device scratch
__device__ float   g_means[NROWS * DD];   // fp32 (exact rescore)
__device__ __half  g_mh[NROWS * DD];      // means (fp16)
__device__ __half  g_ch[KK * DD];         // codebook*2048 (fp16)
__device__ int     g_idx[NROWS];
__device__ float   g_cbsq[KK];
__device__ float   g_spart[4 * KK];       // per-code loss partials (4 e-tiles)
__device__ float4  g_part[NROWS * NCTQ];  // per (row, ctile): v1,i1,v2,i2

// ------------------------------------------------------------- PTX helpers
__device__ __forceinline__ uint32_t smem_u32(const void* p) {
    uint32_t a;
    asm("{ .reg .u64 t; cvta.to.shared.u64 t, %1; cvt.u32.u64 %0, t; }" : "=r"(a) : "l"(p));
    return a;
}
#define CP16(dst, src) \
    asm volatile("cp.async.cg.shared.global [%0], [%1], 16;" :: "r"(dst), "l"(src))
#define CP_COMMIT() asm volatile("cp.async.commit_group;" ::: "memory")
#define CP_WAIT2()  asm volatile("cp.async.wait_group 2;" ::: "memory")
#define LDSM_X4(r0, r1, r2, r3, addr)                                             \
    asm volatile("ldmatrix.sync.aligned.m8n8.x4.shared.b16 {%0,%1,%2,%3}, [%4];"  \
        : "=r"(r0), "=r"(r1), "=r"(r2), "=r"(r3) : "r"(addr))
// fp16-accumulator MMA: D(f16x2 x2) = A*B + D
__device__ __forceinline__ void mma_f16h(uint32_t* d, const uint32_t* a, const uint32_t* b) {
    asm volatile(
        "mma.sync.aligned.m16n8k16.row.col.f16.f16.f16.f16 "
        "{%0,%1}, {%2,%3,%4,%5}, {%6,%7}, {%0,%1};"
        : "+r"(d[0]), "+r"(d[1])
        : "r"(a[0]), "r"(a[1]), "r"(a[2]), "r"(a[3]), "r"(b[0]), "r"(b[1]));
}
__device__ __forceinline__ uint32_t pack_h2(__half a, __half b) {
    return (uint32_t)__half_as_ushort(a) | ((uint32_t)__half_as_ushort(b) << 16);
}

// ------------------------------------------------------------- K1: means + fp16
__global__ void means_kernel(const float4* __restrict__ E) {
    int i = blockIdx.x * blockDim.x + threadIdx.x;
    const int D4 = DD / 4;
    if (i >= NROWS * D4) return;
    int row = i / D4, d4 = i - row * D4;
    float4 a = E[(2 * row) * D4 + d4];
    float4 b = E[(2 * row + 1) * D4 + d4];
    float4 m;
    m.x = 0.5f * (a.x + b.x); m.y = 0.5f * (a.y + b.y);
    m.z = 0.5f * (a.z + b.z); m.w = 0.5f * (a.w + b.w);
    ((float4*)g_means)[i] = m;
    ((uint2*)g_mh)[i] = make_uint2(
        pack_h2(__float2half_rn(m.x), __float2half_rn(m.y)),
        pack_h2(__float2half_rn(m.z), __float2half_rn(m.w)));
}

// ------------------------------------------------------------- K1b: cbsq + fp16 codebook (warp/code)
__global__ __launch_bounds__(256) void cbprep_kernel(const float4* __restrict__ Cb4) {
    int warp = threadIdx.x >> 5, lane = threadIdx.x & 31;
    int k = blockIdx.x * 8 + warp;
    const float4* src = Cb4 + (size_t)k * (DD / 4);
    uint2* dst = (uint2*)g_ch + (size_t)k * (DD / 4);
    float sq = 0.f;
    #pragma unroll
    for (int j = 0; j < 4; j++) {
        float4 v = src[lane + 32 * j];
        sq = fmaf(v.x, v.x, fmaf(v.y, v.y, fmaf(v.z, v.z, fmaf(v.w, v.w, sq))));
        dst[lane + 32 * j] = make_uint2(
            pack_h2(__float2half_rn(v.x * CBSCALE), __float2half_rn(v.y * CBSCALE)),
            pack_h2(__float2half_rn(v.z * CBSCALE), __float2half_rn(v.w * CBSCALE)));
    }
    #pragma unroll
    for (int o = 16; o; o >>= 1) sq += __shfl_xor_sync(0xffffffffu, sq, o);
    if (lane == 0) g_cbsq[k] = sq;
}

// ------------------------------------------------------------- K2: prep GEMM  P=C@W^T tile + loss partials
// grid (16 code-tiles, 4 e-tiles), 256 threads, 128x128 tile, 8x8 micro (R2 pattern).
__global__ __launch_bounds__(256) void prep_gemm(const float* __restrict__ Cb,
                                                 const float* __restrict__ W,
                                                 const float* __restrict__ bias) {
    __shared__ float Cs[8][128];
    __shared__ float Ws[8][128];
    int tid = threadIdx.x;
    int tx = tid & 15, ty = tid >> 4;
    int k0 = blockIdx.x * 128, e0 = blockIdx.y * 128;

    float acc[8][8];
    #pragma unroll
    for (int r = 0; r < 8; r++)
        #pragma unroll
        for (int c = 0; c < 8; c++) acc[r][c] = 0.f;

    const int ldr = tid >> 1, koff = (tid & 1) * 4;
    for (int d0 = 0; d0 < DD; d0 += 8) {
        float4 vc = *(const float4*)&Cb[(size_t)(k0 + ldr) * DD + d0 + koff];
        float4 vw = *(const float4*)&W[(size_t)(e0 + ldr) * DD + d0 + koff];
        Cs[koff + 0][ldr] = vc.x; Cs[koff + 1][ldr] = vc.y;
        Cs[koff + 2][ldr] = vc.z; Cs[koff + 3][ldr] = vc.w;
        Ws[koff + 0][ldr] = vw.x; Ws[koff + 1][ldr] = vw.y;
        Ws[koff + 2][ldr] = vw.z; Ws[koff + 3][ldr] = vw.w;
        __syncthreads();
        #pragma unroll
        for (int kkk = 0; kkk < 8; kkk++) {
            float a[8], b[8];
            *(float4*)(a)     = *(const float4*)&Cs[kkk][ty * 8];
            *(float4*)(a + 4) = *(const float4*)&Cs[kkk][ty * 8 + 4];
            *(float4*)(b)     = *(const float4*)&Ws[kkk][tx * 8];
            *(float4*)(b + 4) = *(const float4*)&Ws[kkk][tx * 8 + 4];
            #pragma unroll
            for (int r = 0; r < 8; r++)
                #pragma unroll
                for (int c = 0; c < 8; c++)
                    acc[r][c] = fmaf(a[r], b[c], acc[r][c]);
        }
        __syncthreads();
    }
    // epilogue: (P + b - C)^2, row partial sums; reduce across tx (16-lane half-warp)
    #pragma unroll
    for (int r = 0; r < 8; r++) {
        int k = k0 + ty * 8 + r;
        float s = 0.f;
        #pragma unroll
        for (int c = 0; c < 8; c++) {
            int e = e0 + tx * 8 + c;
            float diff = acc[r][c] + bias[e] - Cb[(size_t)k * DD + e];
            s = fmaf(diff, diff, s);
        }
        #pragma unroll
        for (int o = 1; o < 16; o <<= 1) s += __shfl_xor_sync(0xffffffffu, s, o);
        if (tx == 0) g_spart[blockIdx.y * KK + k] = s;
    }
}

// ------------------------------------------------------------- K3: fp16-acc GEMM + top-2
// CTA tile 256x128, 512 threads, 16 warps (4x4), warp tile 64x32, 1 CTA/SM.
// 4-buffer circular cp.async pipeline, one __syncthreads per stage, prefetch 3 ahead.
// smem: A[4x32K @0) B[4x16K @131072) cbs@196608. red aliases A0.
#define SMEM_GEMM 197120

__global__ __launch_bounds__(512, 1) void gemm_argmin() {
    extern __shared__ char smraw[];
    uint32_t sb = smem_u32(smraw);
    int tid = threadIdx.x;
    int lane = tid & 31, wid = tid >> 5;
    int wm = wid >> 2, wn = wid & 3;        // warp tile: rows wm*64, cols wn*32
    int row0 = blockIdx.x * MT;
    int ctbase = blockIdx.y * NT;

    uint32_t smA[4], smB[4];
    #pragma unroll
    for (int b = 0; b < 4; b++) {
        smA[b] = sb + b * 32768;
        smB[b] = sb + 131072 + b * 16384;
    }
    float* cbs = (float*)(smraw + 196608);
    float4* red = (float4*)smraw;           // alias: used only after mainloop

    if (tid < NT) cbs[tid] = g_cbsq[ctbase + tid] * CBSCALE;

    // ldmatrix lane-invariants
    const int rA = lane & 15, cA = lane >> 4;
    const int rB = (lane & 7) | ((lane >> 4) << 3);
    const int cB = (lane >> 3) & 1;

    uint32_t acc[4][4][2];                  // f16x2 accumulators
    #pragma unroll
    for (int a = 0; a < 4; a++)
        #pragma unroll
        for (int b = 0; b < 4; b++) { acc[a][b][0] = 0u; acc[a][b][1] = 0u; }

    const int arow = tid >> 1, ah4 = (tid & 1) * 4;
    const int brow = tid >> 2, bc2 = (tid & 3) * 2;

    auto issue = [&](int s, int b) {
        {
            uint32_t x = (uint32_t)(arow & 7);
            const __half* p = g_mh + (size_t)(row0 + arow) * DD + s * KC + ah4 * 8;
            uint32_t base = smA[b] + arow * 128;
            #pragma unroll
            for (int c = 0; c < 4; c++)
                CP16(base + ((((uint32_t)(ah4 + c)) ^ x) << 4), p + 8 * c);
        }
        {
            uint32_t x = (uint32_t)(brow & 7);
            const __half* p = g_ch + (size_t)(ctbase + brow) * DD + s * KC + bc2 * 8;
            uint32_t base = smB[b] + brow * 128;
            CP16(base + ((((uint32_t)bc2) ^ x) << 4), p);
            CP16(base + ((((uint32_t)(bc2 + 1)) ^ x) << 4), p + 8);
        }
    };

    issue(0, 0); CP_COMMIT();
    issue(1, 1); CP_COMMIT();
    issue(2, 2); CP_COMMIT();

    for (int s = 0; s < NSTAGE; s++) {
        const int b = s & 3;
        CP_WAIT2();
        __syncthreads();
        if (s + 3 < NSTAGE) issue(s + 3, (s + 3) & 3);
        CP_COMMIT();

        #pragma unroll
        for (int kk = 0; kk < 4; kk++) {
            uint32_t ah[4][4], bh[4][2];
            #pragma unroll
            for (int mf = 0; mf < 4; mf++) {
                int row = wm * 64 + mf * 16 + rA;
                uint32_t ba = smA[b] + row * 128;
                uint32_t x = (uint32_t)(row & 7);
                LDSM_X4(ah[mf][0], ah[mf][1], ah[mf][2], ah[mf][3],
                        ba + ((((uint32_t)(2 * kk + cA)) ^ x) << 4));
            }
            #pragma unroll
            for (int np = 0; np < 2; np++) {
                int n = wn * 32 + np * 16 + rB;
                uint32_t bb = smB[b] + n * 128;
                uint32_t x = (uint32_t)(n & 7);
                uint32_t t0, t1, t2, t3;
                LDSM_X4(t0, t1, t2, t3, bb + ((((uint32_t)(2 * kk + cB)) ^ x) << 4));
                bh[2 * np][0] = t0; bh[2 * np][1] = t1;
                bh[2 * np + 1][0] = t2; bh[2 * np + 1][1] = t3;
            }
            #pragma unroll
            for (int mf = 0; mf < 4; mf++)
                #pragma unroll
                for (int nf = 0; nf < 4; nf++)
                    mma_f16h(acc[mf][nf], ah[mf], bh[nf]);
        }
    }
    __syncthreads();   // before aliasing smA as red[]

    // ---- epilogue: scores + per-row top-2 (f16x2 acc: reg[half] = cols 2q,2q+1, row g+8*half) ----
    int g = lane >> 2, q = lane & 3;
    #pragma unroll
    for (int mf = 0; mf < 4; mf++) {
        #pragma unroll
        for (int half = 0; half < 2; half++) {
            int rloc = wm * 64 + mf * 16 + half * 8 + g;
            float v1 = 3.4e38f, v2 = 3.4e38f;
            int i1 = 0, i2 = 0;
            #pragma unroll
            for (int nf = 0; nf < 4; nf++) {
                uint32_t pr = acc[mf][nf][half];
                __half2 h2 = *reinterpret_cast<__half2*>(&pr);
                float dv[2] = { __low2float(h2), __high2float(h2) };
                #pragma unroll
                for (int j = 0; j < 2; j++) {
                    int cloc = wn * 32 + nf * 8 + 2 * q + j;
                    float sc = fmaf(-2.0f, dv[j], cbs[cloc]);
                    int code = ctbase + cloc;
                    if (sc < v1) { v2 = v1; i2 = i1; v1 = sc; i1 = code; }
                    else if (sc < v2) { v2 = sc; i2 = code; }
                }
            }
            #pragma unroll
            for (int o = 1; o <= 2; o <<= 1) {
                float w1 = __shfl_xor_sync(0xffffffffu, v1, o);
                int   j1 = __shfl_xor_sync(0xffffffffu, i1, o);
                float w2 = __shfl_xor_sync(0xffffffffu, v2, o);
                int   j2 = __shfl_xor_sync(0xffffffffu, i2, o);
                if (w1 < v1 || (w1 == v1 && j1 < i1)) { v2 = v1; i2 = i1; v1 = w1; i1 = j1; }
                else if (w1 < v2 || (w1 == v2 && j1 < i2)) { v2 = w1; i2 = j1; }
                if (w2 < v1 || (w2 == v1 && j2 < i1)) { v2 = v1; i2 = i1; v1 = w2; i1 = j2; }
                else if (w2 < v2 || (w2 == v2 && j2 < i2)) { v2 = w2; i2 = j2; }
            }
            if (q == 0)
                red[rloc * 4 + wn] =
                    make_float4(v1, __int_as_float(i1), v2, __int_as_float(i2));
        }
    }
    __syncthreads();
    if (tid < MT) {
        float v1 = 3.4e38f, v2 = 3.4e38f;
        int i1 = 0x7fffffff, i2 = 0x7fffffff;
        #pragma unroll
        for (int w = 0; w < 4; w++) {
            float4 p = red[tid * 4 + w];
            float w1 = p.x, w2 = p.z;
            int j1 = __float_as_int(p.y), j2 = __float_as_int(p.w);
            if (w1 < v1 || (w1 == v1 && j1 < i1)) { v2 = v1; i2 = i1; v1 = w1; i1 = j1; }
            else if (w1 < v2 || (w1 == v2 && j1 < i2)) { v2 = w1; i2 = j1; }
            if (w2 < v1 || (w2 == v1 && j2 < i1)) { v2 = v1; i2 = i1; v1 = w2; i1 = j2; }
            else if (w2 < v2 || (w2 == v2 && j2 < i2)) { v2 = w2; i2 = j2; }
        }
        g_part[(size_t)(row0 + tid) * NCTQ + blockIdx.y] =
            make_float4(v1, __int_as_float(i1), v2, __int_as_float(i2));
    }
}

// ------------------------------------------------------------- K4: margin-pruned exact rescore
__global__ __launch_bounds__(256) void combine_kernel(const float* __restrict__ Cb,
                                                      float* __restrict__ out_idx_f,
                                                      float4* __restrict__ out_emb4) {
    int row = blockIdx.x * 8 + (threadIdx.x >> 5);
    int lane = threadIdx.x & 31;

    float4 p = g_part[(size_t)row * NCTQ + (lane & 15)];
    float v  = (lane < 16) ? p.x : p.z;
    int   ci = (lane < 16) ? __float_as_int(p.y) : __float_as_int(p.w);

    float vmin = v;
    #pragma unroll
    for (int o = 16; o; o >>= 1) vmin = fminf(vmin, __shfl_xor_sync(0xffffffffu, vmin, o));

    unsigned mask = __ballot_sync(0xffffffffu, v <= vmin + MARGIN);

    const float4* m4 = (const float4*)&g_means[(size_t)row * DD];
    float bv = 3.4e38f;
    int bi = 0x7fffffff;
    while (mask) {
        int src = __ffs(mask) - 1;
        mask &= mask - 1;
        int cand = __shfl_sync(0xffffffffu, ci, src);
        const float4* c4 = (const float4*)&Cb[(size_t)cand * DD];
        float a0 = 0.f, a1 = 0.f, a2 = 0.f, a3 = 0.f;
        #pragma unroll
        for (int j = 0; j < 4; j++) {
            float4 mv = m4[lane + 32 * j];
            float4 cv = c4[lane + 32 * j];
            a0 = fmaf(mv.x, cv.x, a0);
            a1 = fmaf(mv.y, cv.y, a1);
            a2 = fmaf(mv.z, cv.z, a2);
            a3 = fmaf(mv.w, cv.w, a3);
        }
        float dot = (a0 + a1) + (a2 + a3);
        #pragma unroll
        for (int o = 16; o; o >>= 1) dot += __shfl_xor_sync(0xffffffffu, dot, o);
        float sv = fmaf(-2.f, dot, g_cbsq[cand]);
        if (sv < bv || (sv == bv && cand < bi)) { bv = sv; bi = cand; }
    }
    if (lane == 0) {
        g_idx[row] = bi;
        out_idx_f[row] = (float)bi;
    }
    const float4* src4 = (const float4*)&Cb[(size_t)bi * DD];
    float4* dst = out_emb4 + (size_t)row * (DD / 4);
    #pragma unroll
    for (int j = 0; j < 4; j++)
        dst[lane + 32 * j] = src4[lane + 32 * j];
}

// ------------------------------------------------------------- K5: loss (sums 4 e-tile partials)
__global__ void loss_kernel(float* __restrict__ out_loss) {
    __shared__ float red[1024];
    float s = 0.f;
    for (int n = threadIdx.x; n < NROWS; n += 1024) {
        int k = g_idx[n];
        s += (g_spart[k] + g_spart[KK + k]) + (g_spart[2 * KK + k] + g_spart[3 * KK + k]);
    }
    red[threadIdx.x] = s;
    __syncthreads();
    for (int st = 512; st > 0; st >>= 1) {
        if (threadIdx.x < st) red[threadIdx.x] += red[threadIdx.x + st];
        __syncthreads();
    }
    if (threadIdx.x == 0)
        out_loss[0] = red[0] / (float)((long long)NROWS * DD);
}

// -------------------------------------------------------------
extern "C" void kernel_launch(void* const* d_in, const int* in_sizes, int n_in,
                              void* d_out, int out_size) {
    const float* E    = (const float*)d_in[1];
    const float* Cb   = (const float*)d_in[2];
    const float* W    = (const float*)d_in[3];
    const float* bias = (const float*)d_in[4];

    float* out      = (float*)d_out;
    float* out_idx  = out;
    float* out_emb  = out + NROWS;
    float* out_loss = out + NROWS + NROWS * DD;

    cudaFuncSetAttribute(gemm_argmin, cudaFuncAttributeMaxDynamicSharedMemorySize, SMEM_GEMM);

    means_kernel<<<(NROWS * (DD / 4) + 255) / 256, 256>>>((const float4*)E);
    cbprep_kernel<<<KK / 8, 256>>>((const float4*)Cb);
    prep_gemm<<<dim3(16, 4), 256>>>(Cb, W, bias);
    gemm_argmin<<<dim3(NROWS / MT, NCTQ), 512, SMEM_GEMM>>>();
    combine_kernel<<<NROWS / 8, 256>>>(Cb, out_idx, (float4*)out_emb);
    loss_kernel<<<1, 1024>>>(out_loss);
}

// round 15
// speedup vs baseline: 1.6511x; 1.1247x over previous
#include <cuda_runtime.h>
#include <cuda_fp16.h>
#include <cstdint>

#define BB 16
#define LL 4096
#define DD 512
#define KK 2048
#define NROWS 32768

#define MT 256            // rows per CTA
#define NT 256            // codes per CTA
#define KC 64             // k elems per stage (128B rows)
#define NSTAGE (DD / KC)  // 8
#define NCTQ (KK / NT)    // 8
#define CBSCALE 2048.0f   // codebook scale: argmin-invariant, keeps fp16 in range
#define MARGIN 3.0f       // rescore margin (scaled units) >> fp16+f16acc score err (~0.2)

// ------------------------------------------------------------- device scratch
__device__ float   g_means[NROWS * DD];   // fp32 (exact rescore)
__device__ __half  g_mh[NROWS * DD];      // means (fp16)
__device__ __half  g_ch[KK * DD];         // codebook*2048 (fp16)
__device__ int     g_idx[NROWS];
__device__ float   g_cbsq[KK];
__device__ float   g_spart[4 * KK];       // per-code loss partials (4 e-tiles)
__device__ float4  g_part[NROWS * NCTQ];  // per (row, ctile): v1,i1,v2,i2

// ------------------------------------------------------------- PTX helpers
__device__ __forceinline__ uint32_t smem_u32(const void* p) {
    uint32_t a;
    asm("{ .reg .u64 t; cvta.to.shared.u64 t, %1; cvt.u32.u64 %0, t; }" : "=r"(a) : "l"(p));
    return a;
}
#define CP16(dst, src) \
    asm volatile("cp.async.cg.shared.global [%0], [%1], 16;" :: "r"(dst), "l"(src))
#define CP_COMMIT() asm volatile("cp.async.commit_group;" ::: "memory")
#define CP_WAIT1()  asm volatile("cp.async.wait_group 1;" ::: "memory")
#define LDSM_X4(r0, r1, r2, r3, addr)                                             \
    asm volatile("ldmatrix.sync.aligned.m8n8.x4.shared.b16 {%0,%1,%2,%3}, [%4];"  \
        : "=r"(r0), "=r"(r1), "=r"(r2), "=r"(r3) : "r"(addr))
// fp16-accumulator MMA: D(f16x2 x2) = A*B + D
__device__ __forceinline__ void mma_f16h(uint32_t* d, const uint32_t* a, const uint32_t* b) {
    asm volatile(
        "mma.sync.aligned.m16n8k16.row.col.f16.f16.f16.f16 "
        "{%0,%1}, {%2,%3,%4,%5}, {%6,%7}, {%0,%1};"
        : "+r"(d[0]), "+r"(d[1])
        : "r"(a[0]), "r"(a[1]), "r"(a[2]), "r"(a[3]), "r"(b[0]), "r"(b[1]));
}
__device__ __forceinline__ uint32_t pack_h2(__half a, __half b) {
    return (uint32_t)__half_as_ushort(a) | ((uint32_t)__half_as_ushort(b) << 16);
}

// ------------------------------------------------------------- K1: means + fp16
__global__ void means_kernel(const float4* __restrict__ E) {
    int i = blockIdx.x * blockDim.x + threadIdx.x;
    const int D4 = DD / 4;
    if (i >= NROWS * D4) return;
    int row = i / D4, d4 = i - row * D4;
    float4 a = E[(2 * row) * D4 + d4];
    float4 b = E[(2 * row + 1) * D4 + d4];
    float4 m;
    m.x = 0.5f * (a.x + b.x); m.y = 0.5f * (a.y + b.y);
    m.z = 0.5f * (a.z + b.z); m.w = 0.5f * (a.w + b.w);
    ((float4*)g_means)[i] = m;
    ((uint2*)g_mh)[i] = make_uint2(
        pack_h2(__float2half_rn(m.x), __float2half_rn(m.y)),
        pack_h2(__float2half_rn(m.z), __float2half_rn(m.w)));
}

// ------------------------------------------------------------- K1b: cbsq + fp16 codebook (warp/code)
__global__ __launch_bounds__(256) void cbprep_kernel(const float4* __restrict__ Cb4) {
    int warp = threadIdx.x >> 5, lane = threadIdx.x & 31;
    int k = blockIdx.x * 8 + warp;
    const float4* src = Cb4 + (size_t)k * (DD / 4);
    uint2* dst = (uint2*)g_ch + (size_t)k * (DD / 4);
    float sq = 0.f;
    #pragma unroll
    for (int j = 0; j < 4; j++) {
        float4 v = src[lane + 32 * j];
        sq = fmaf(v.x, v.x, fmaf(v.y, v.y, fmaf(v.z, v.z, fmaf(v.w, v.w, sq))));
        dst[lane + 32 * j] = make_uint2(
            pack_h2(__float2half_rn(v.x * CBSCALE), __float2half_rn(v.y * CBSCALE)),
            pack_h2(__float2half_rn(v.z * CBSCALE), __float2half_rn(v.w * CBSCALE)));
    }
    #pragma unroll
    for (int o = 16; o; o >>= 1) sq += __shfl_xor_sync(0xffffffffu, sq, o);
    if (lane == 0) g_cbsq[k] = sq;
}

// ------------------------------------------------------------- K2: prep GEMM  P=C@W^T + loss partials
__global__ __launch_bounds__(256) void prep_gemm(const float* __restrict__ Cb,
                                                 const float* __restrict__ W,
                                                 const float* __restrict__ bias) {
    __shared__ float Cs[8][128];
    __shared__ float Ws[8][128];
    int tid = threadIdx.x;
    int tx = tid & 15, ty = tid >> 4;
    int k0 = blockIdx.x * 128, e0 = blockIdx.y * 128;

    float acc[8][8];
    #pragma unroll
    for (int r = 0; r < 8; r++)
        #pragma unroll
        for (int c = 0; c < 8; c++) acc[r][c] = 0.f;

    const int ldr = tid >> 1, koff = (tid & 1) * 4;
    for (int d0 = 0; d0 < DD; d0 += 8) {
        float4 vc = *(const float4*)&Cb[(size_t)(k0 + ldr) * DD + d0 + koff];
        float4 vw = *(const float4*)&W[(size_t)(e0 + ldr) * DD + d0 + koff];
        Cs[koff + 0][ldr] = vc.x; Cs[koff + 1][ldr] = vc.y;
        Cs[koff + 2][ldr] = vc.z; Cs[koff + 3][ldr] = vc.w;
        Ws[koff + 0][ldr] = vw.x; Ws[koff + 1][ldr] = vw.y;
        Ws[koff + 2][ldr] = vw.z; Ws[koff + 3][ldr] = vw.w;
        __syncthreads();
        #pragma unroll
        for (int kkk = 0; kkk < 8; kkk++) {
            float a[8], b[8];
            *(float4*)(a)     = *(const float4*)&Cs[kkk][ty * 8];
            *(float4*)(a + 4) = *(const float4*)&Cs[kkk][ty * 8 + 4];
            *(float4*)(b)     = *(const float4*)&Ws[kkk][tx * 8];
            *(float4*)(b + 4) = *(const float4*)&Ws[kkk][tx * 8 + 4];
            #pragma unroll
            for (int r = 0; r < 8; r++)
                #pragma unroll
                for (int c = 0; c < 8; c++)
                    acc[r][c] = fmaf(a[r], b[c], acc[r][c]);
        }
        __syncthreads();
    }
    #pragma unroll
    for (int r = 0; r < 8; r++) {
        int k = k0 + ty * 8 + r;
        float s = 0.f;
        #pragma unroll
        for (int c = 0; c < 8; c++) {
            int e = e0 + tx * 8 + c;
            float diff = acc[r][c] + bias[e] - Cb[(size_t)k * DD + e];
            s = fmaf(diff, diff, s);
        }
        #pragma unroll
        for (int o = 1; o < 16; o <<= 1) s += __shfl_xor_sync(0xffffffffu, s, o);
        if (tx == 0) g_spart[blockIdx.y * KK + k] = s;
    }
}

// ------------------------------------------------------------- K3: fp16-acc GEMM 256x256 + top-2
// 512 threads, 16 warps (4x4), warp tile 64x64, 1 CTA/SM.
// 3-buffer circular cp.async pipeline, one __syncthreads/stage, prefetch 2 ahead.
// Rows: 128B = 64 fp16 of one k-stage, 16B chunks XOR-swizzled by row&7.
// smem: A[3x32K @0) B[3x32K @98304) cbs(1KB)@196608. red (16KB) aliases A0.
#define SMEM_GEMM 197632

__global__ __launch_bounds__(512, 1) void gemm_argmin() {
    extern __shared__ char smraw[];
    uint32_t sb = smem_u32(smraw);
    int tid = threadIdx.x;
    int lane = tid & 31, wid = tid >> 5;
    int wm = wid >> 2, wn = wid & 3;        // warp tile: rows wm*64, cols wn*64
    int row0 = blockIdx.x * MT;
    int ctbase = blockIdx.y * NT;

    uint32_t smA[3], smB[3];
    #pragma unroll
    for (int b = 0; b < 3; b++) {
        smA[b] = sb + b * 32768;
        smB[b] = sb + 98304 + b * 32768;
    }
    float* cbs = (float*)(smraw + 196608);
    float4* red = (float4*)smraw;           // alias: used only after mainloop (16KB < 32KB)

    if (tid < NT) cbs[tid] = g_cbsq[ctbase + tid] * CBSCALE;

    // ldmatrix lane-invariants
    const int rA = lane & 15, cA = lane >> 4;
    const int rB = (lane & 7) | ((lane >> 4) << 3);
    const int cB = (lane >> 3) & 1;

    uint32_t acc[4][8][2];                  // f16x2 accumulators (64 regs)
    #pragma unroll
    for (int a = 0; a < 4; a++)
        #pragma unroll
        for (int b = 0; b < 8; b++) { acc[a][b][0] = 0u; acc[a][b][1] = 0u; }

    // loaders: A and B each 256 rows x 128B; 2 threads/row, 64B each
    const int arow = tid >> 1, ah4 = (tid & 1) * 4;

    auto issue = [&](int s, int b) {
        uint32_t x = (uint32_t)(arow & 7);
        {
            const __half* p = g_mh + (size_t)(row0 + arow) * DD + s * KC + ah4 * 8;
            uint32_t base = smA[b] + arow * 128;
            #pragma unroll
            for (int c = 0; c < 4; c++)
                CP16(base + ((((uint32_t)(ah4 + c)) ^ x) << 4), p + 8 * c);
        }
        {
            const __half* p = g_ch + (size_t)(ctbase + arow) * DD + s * KC + ah4 * 8;
            uint32_t base = smB[b] + arow * 128;
            #pragma unroll
            for (int c = 0; c < 4; c++)
                CP16(base + ((((uint32_t)(ah4 + c)) ^ x) << 4), p + 8 * c);
        }
    };

    issue(0, 0); CP_COMMIT();
    issue(1, 1); CP_COMMIT();

    for (int s = 0; s < NSTAGE; s++) {
        const int b = s % 3;
        CP_WAIT1();             // group s complete (issued so far = s+2)
        __syncthreads();        // all warps done reading buf (s-1)%3 == (s+2)%3
        if (s + 2 < NSTAGE) { issue(s + 2, (s + 2) % 3); CP_COMMIT(); }

        #pragma unroll
        for (int kk = 0; kk < 4; kk++) {
            uint32_t ah[4][4], bh[8][2];
            #pragma unroll
            for (int mf = 0; mf < 4; mf++) {
                int row = wm * 64 + mf * 16 + rA;
                uint32_t ba = smA[b] + row * 128;
                uint32_t x = (uint32_t)(row & 7);
                LDSM_X4(ah[mf][0], ah[mf][1], ah[mf][2], ah[mf][3],
                        ba + ((((uint32_t)(2 * kk + cA)) ^ x) << 4));
            }
            #pragma unroll
            for (int np = 0; np < 4; np++) {
                int n = wn * 64 + np * 16 + rB;
                uint32_t bb = smB[b] + n * 128;
                uint32_t x = (uint32_t)(n & 7);
                uint32_t t0, t1, t2, t3;
                LDSM_X4(t0, t1, t2, t3, bb + ((((uint32_t)(2 * kk + cB)) ^ x) << 4));
                bh[2 * np][0] = t0; bh[2 * np][1] = t1;
                bh[2 * np + 1][0] = t2; bh[2 * np + 1][1] = t3;
            }
            #pragma unroll
            for (int mf = 0; mf < 4; mf++)
                #pragma unroll
                for (int nf = 0; nf < 8; nf++)
                    mma_f16h(acc[mf][nf], ah[mf], bh[nf]);
        }
    }
    __syncthreads();   // before aliasing smA as red[]

    // ---- epilogue: scores + per-row top-2 ----
    int g = lane >> 2, q = lane & 3;
    #pragma unroll
    for (int mf = 0; mf < 4; mf++) {
        #pragma unroll
        for (int half = 0; half < 2; half++) {
            int rloc = wm * 64 + mf * 16 + half * 8 + g;
            float v1 = 3.4e38f, v2 = 3.4e38f;
            int i1 = 0, i2 = 0;
            #pragma unroll
            for (int nf = 0; nf < 8; nf++) {
                uint32_t pr = acc[mf][nf][half];
                __half2 h2 = *reinterpret_cast<__half2*>(&pr);
                float dv[2] = { __low2float(h2), __high2float(h2) };
                #pragma unroll
                for (int j = 0; j < 2; j++) {
                    int cloc = wn * 64 + nf * 8 + 2 * q + j;
                    float sc = fmaf(-2.0f, dv[j], cbs[cloc]);
                    int code = ctbase + cloc;
                    if (sc < v1) { v2 = v1; i2 = i1; v1 = sc; i1 = code; }
                    else if (sc < v2) { v2 = sc; i2 = code; }
                }
            }
            #pragma unroll
            for (int o = 1; o <= 2; o <<= 1) {
                float w1 = __shfl_xor_sync(0xffffffffu, v1, o);
                int   j1 = __shfl_xor_sync(0xffffffffu, i1, o);
                float w2 = __shfl_xor_sync(0xffffffffu, v2, o);
                int   j2 = __shfl_xor_sync(0xffffffffu, i2, o);
                if (w1 < v1 || (w1 == v1 && j1 < i1)) { v2 = v1; i2 = i1; v1 = w1; i1 = j1; }
                else if (w1 < v2 || (w1 == v2 && j1 < i2)) { v2 = w1; i2 = j1; }
                if (w2 < v1 || (w2 == v1 && j2 < i1)) { v2 = v1; i2 = i1; v1 = w2; i1 = j2; }
                else if (w2 < v2 || (w2 == v2 && j2 < i2)) { v2 = w2; i2 = j2; }
            }
            if (q == 0)
                red[rloc * 4 + wn] =
                    make_float4(v1, __int_as_float(i1), v2, __int_as_float(i2));
        }
    }
    __syncthreads();
    if (tid < MT) {
        float v1 = 3.4e38f, v2 = 3.4e38f;
        int i1 = 0x7fffffff, i2 = 0x7fffffff;
        #pragma unroll
        for (int w = 0; w < 4; w++) {
            float4 p = red[tid * 4 + w];
            float w1 = p.x, w2 = p.z;
            int j1 = __float_as_int(p.y), j2 = __float_as_int(p.w);
            if (w1 < v1 || (w1 == v1 && j1 < i1)) { v2 = v1; i2 = i1; v1 = w1; i1 = j1; }
            else if (w1 < v2 || (w1 == v2 && j1 < i2)) { v2 = w1; i2 = j1; }
            if (w2 < v1 || (w2 == v1 && j2 < i1)) { v2 = v1; i2 = i1; v1 = w2; i1 = j2; }
            else if (w2 < v2 || (w2 == v2 && j2 < i2)) { v2 = w2; i2 = j2; }
        }
        g_part[(size_t)(row0 + tid) * NCTQ + blockIdx.y] =
            make_float4(v1, __int_as_float(i1), v2, __int_as_float(i2));
    }
}

// ------------------------------------------------------------- K4: margin-pruned exact rescore
// Warp per row: 16 candidates (top-2 x 8 tiles) in lanes 0-15; lanes 16-31 inert.
__global__ __launch_bounds__(256) void combine_kernel(const float* __restrict__ Cb,
                                                      float* __restrict__ out_idx_f,
                                                      float4* __restrict__ out_emb4) {
    int row = blockIdx.x * 8 + (threadIdx.x >> 5);
    int lane = threadIdx.x & 31;

    float v = 3.4e38f;
    int ci = 0x7fffffff;
    if (lane < 16) {
        float4 p = g_part[(size_t)row * NCTQ + (lane & 7)];
        v  = (lane < 8) ? p.x : p.z;
        ci = (lane < 8) ? __float_as_int(p.y) : __float_as_int(p.w);
    }

    float vmin = v;
    #pragma unroll
    for (int o = 16; o; o >>= 1) vmin = fminf(vmin, __shfl_xor_sync(0xffffffffu, vmin, o));

    unsigned mask = __ballot_sync(0xffffffffu, v <= vmin + MARGIN);

    const float4* m4 = (const float4*)&g_means[(size_t)row * DD];
    float bv = 3.4e38f;
    int bi = 0x7fffffff;
    while (mask) {
        int src = __ffs(mask) - 1;
        mask &= mask - 1;
        int cand = __shfl_sync(0xffffffffu, ci, src);
        const float4* c4 = (const float4*)&Cb[(size_t)cand * DD];
        float a0 = 0.f, a1 = 0.f, a2 = 0.f, a3 = 0.f;
        #pragma unroll
        for (int j = 0; j < 4; j++) {
            float4 mv = m4[lane + 32 * j];
            float4 cv = c4[lane + 32 * j];
            a0 = fmaf(mv.x, cv.x, a0);
            a1 = fmaf(mv.y, cv.y, a1);
            a2 = fmaf(mv.z, cv.z, a2);
            a3 = fmaf(mv.w, cv.w, a3);
        }
        float dot = (a0 + a1) + (a2 + a3);
        #pragma unroll
        for (int o = 16; o; o >>= 1) dot += __shfl_xor_sync(0xffffffffu, dot, o);
        float sv = fmaf(-2.f, dot, g_cbsq[cand]);
        if (sv < bv || (sv == bv && cand < bi)) { bv = sv; bi = cand; }
    }
    if (lane == 0) {
        g_idx[row] = bi;
        out_idx_f[row] = (float)bi;
    }
    const float4* src4 = (const float4*)&Cb[(size_t)bi * DD];
    float4* dst = out_emb4 + (size_t)row * (DD / 4);
    #pragma unroll
    for (int j = 0; j < 4; j++)
        dst[lane + 32 * j] = src4[lane + 32 * j];
}

// ------------------------------------------------------------- K5: loss (sums 4 e-tile partials)
__global__ void loss_kernel(float* __restrict__ out_loss) {
    __shared__ float red[1024];
    float s = 0.f;
    for (int n = threadIdx.x; n < NROWS; n += 1024) {
        int k = g_idx[n];
        s += (g_spart[k] + g_spart[KK + k]) + (g_spart[2 * KK + k] + g_spart[3 * KK + k]);
    }
    red[threadIdx.x] = s;
    __syncthreads();
    for (int st = 512; st > 0; st >>= 1) {
        if (threadIdx.x < st) red[threadIdx.x] += red[threadIdx.x + st];
        __syncthreads();
    }
    if (threadIdx.x == 0)
        out_loss[0] = red[0] / (float)((long long)NROWS * DD);
}

// -------------------------------------------------------------
extern "C" void kernel_launch(void* const* d_in, const int* in_sizes, int n_in,
                              void* d_out, int out_size) {
    const float* E    = (const float*)d_in[1];
    const float* Cb   = (const float*)d_in[2];
    const float* W    = (const float*)d_in[3];
    const float* bias = (const float*)d_in[4];

    float* out      = (float*)d_out;
    float* out_idx  = out;
    float* out_emb  = out + NROWS;
    float* out_loss = out + NROWS + NROWS * DD;

    cudaFuncSetAttribute(gemm_argmin, cudaFuncAttributeMaxDynamicSharedMemorySize, SMEM_GEMM);

    means_kernel<<<(NROWS * (DD / 4) + 255) / 256, 256>>>((const float4*)E);
    cbprep_kernel<<<KK / 8, 256>>>((const float4*)Cb);
    prep_gemm<<<dim3(16, 4), 256>>>(Cb, W, bias);
    gemm_argmin<<<dim3(NROWS / MT, NCTQ), 512, SMEM_GEMM>>>();
    combine_kernel<<<NROWS / 8, 256>>>(Cb, out_idx, (float4*)out_emb);
    loss_kernel<<<1, 1024>>>(out_loss);
}

// round 16
// speedup vs baseline: 1.7250x; 1.0448x over previous
#include <cuda_runtime.h>
#include <cuda_fp16.h>
#include <cstdint>

#define BB 16
#define LL 4096
#define DD 512
#define KK 2048
#define NROWS 32768

#define MT 256            // rows per CTA
#define NT 256            // codes per CTA
#define KC 64             // k elems per stage (128B rows)
#define NSTAGE (DD / KC)  // 8
#define NCTQ (KK / NT)    // 8
#define CBSCALE 2048.0f   // codebook scale: argmin-invariant, keeps fp16 in range
#define MARGIN 3.0f       // rescore margin (scaled units) >> fp16+f16acc score err (~0.2)

// ------------------------------------------------------------- device scratch
__device__ __half  g_mh[NROWS * DD];      // means (fp16)
__device__ __half  g_ch[KK * DD];         // codebook*2048 (fp16)
__device__ int     g_idx[NROWS];
__device__ float   g_cbsq[KK];
__device__ float   g_spart[4 * KK];       // per-code loss partials (4 e-tiles)
__device__ float   g_lred[64];            // loss block partials
__device__ float4  g_part[NROWS * NCTQ];  // per (row, ctile): v1,i1,v2,i2

// ------------------------------------------------------------- PTX helpers
__device__ __forceinline__ uint32_t smem_u32(const void* p) {
    uint32_t a;
    asm("{ .reg .u64 t; cvta.to.shared.u64 t, %1; cvt.u32.u64 %0, t; }" : "=r"(a) : "l"(p));
    return a;
}
#define CP16(dst, src) \
    asm volatile("cp.async.cg.shared.global [%0], [%1], 16;" :: "r"(dst), "l"(src))
#define CP_COMMIT() asm volatile("cp.async.commit_group;" ::: "memory")
#define CP_WAIT2()  asm volatile("cp.async.wait_group 2;" ::: "memory")
#define LDSM_X4(r0, r1, r2, r3, addr)                                             \
    asm volatile("ldmatrix.sync.aligned.m8n8.x4.shared.b16 {%0,%1,%2,%3}, [%4];"  \
        : "=r"(r0), "=r"(r1), "=r"(r2), "=r"(r3) : "r"(addr))
// fp16-accumulator MMA
__device__ __forceinline__ void mma_f16h(uint32_t* d, const uint32_t* a, const uint32_t* b) {
    asm volatile(
        "mma.sync.aligned.m16n8k16.row.col.f16.f16.f16.f16 "
        "{%0,%1}, {%2,%3,%4,%5}, {%6,%7}, {%0,%1};"
        : "+r"(d[0]), "+r"(d[1])
        : "r"(a[0]), "r"(a[1]), "r"(a[2]), "r"(a[3]), "r"(b[0]), "r"(b[1]));
}
__device__ __forceinline__ uint32_t pack_h2(__half a, __half b) {
    return (uint32_t)__half_as_ushort(a) | ((uint32_t)__half_as_ushort(b) << 16);
}

// ------------------------------------------------------------- K1: means -> fp16 only
__global__ void means_kernel(const float4* __restrict__ E) {
    int i = blockIdx.x * blockDim.x + threadIdx.x;
    const int D4 = DD / 4;
    if (i >= NROWS * D4) return;
    int row = i / D4, d4 = i - row * D4;
    float4 a = E[(2 * row) * D4 + d4];
    float4 b = E[(2 * row + 1) * D4 + d4];
    float4 m;
    m.x = 0.5f * (a.x + b.x); m.y = 0.5f * (a.y + b.y);
    m.z = 0.5f * (a.z + b.z); m.w = 0.5f * (a.w + b.w);
    ((uint2*)g_mh)[i] = make_uint2(
        pack_h2(__float2half_rn(m.x), __float2half_rn(m.y)),
        pack_h2(__float2half_rn(m.z), __float2half_rn(m.w)));
}

// ------------------------------------------------------------- K1b: cbsq + fp16 codebook (warp/code)
__global__ __launch_bounds__(256) void cbprep_kernel(const float4* __restrict__ Cb4) {
    int warp = threadIdx.x >> 5, lane = threadIdx.x & 31;
    int k = blockIdx.x * 8 + warp;
    const float4* src = Cb4 + (size_t)k * (DD / 4);
    uint2* dst = (uint2*)g_ch + (size_t)k * (DD / 4);
    float sq = 0.f;
    #pragma unroll
    for (int j = 0; j < 4; j++) {
        float4 v = src[lane + 32 * j];
        sq = fmaf(v.x, v.x, fmaf(v.y, v.y, fmaf(v.z, v.z, fmaf(v.w, v.w, sq))));
        dst[lane + 32 * j] = make_uint2(
            pack_h2(__float2half_rn(v.x * CBSCALE), __float2half_rn(v.y * CBSCALE)),
            pack_h2(__float2half_rn(v.z * CBSCALE), __float2half_rn(v.w * CBSCALE)));
    }
    #pragma unroll
    for (int o = 16; o; o >>= 1) sq += __shfl_xor_sync(0xffffffffu, sq, o);
    if (lane == 0) g_cbsq[k] = sq;
}

// ------------------------------------------------------------- K2: prep GEMM  P=C@W^T + loss partials
__global__ __launch_bounds__(256) void prep_gemm(const float* __restrict__ Cb,
                                                 const float* __restrict__ W,
                                                 const float* __restrict__ bias) {
    __shared__ float Cs[8][128];
    __shared__ float Ws[8][128];
    int tid = threadIdx.x;
    int tx = tid & 15, ty = tid >> 4;
    int k0 = blockIdx.x * 128, e0 = blockIdx.y * 128;

    float acc[8][8];
    #pragma unroll
    for (int r = 0; r < 8; r++)
        #pragma unroll
        for (int c = 0; c < 8; c++) acc[r][c] = 0.f;

    const int ldr = tid >> 1, koff = (tid & 1) * 4;
    for (int d0 = 0; d0 < DD; d0 += 8) {
        float4 vc = *(const float4*)&Cb[(size_t)(k0 + ldr) * DD + d0 + koff];
        float4 vw = *(const float4*)&W[(size_t)(e0 + ldr) * DD + d0 + koff];
        Cs[koff + 0][ldr] = vc.x; Cs[koff + 1][ldr] = vc.y;
        Cs[koff + 2][ldr] = vc.z; Cs[koff + 3][ldr] = vc.w;
        Ws[koff + 0][ldr] = vw.x; Ws[koff + 1][ldr] = vw.y;
        Ws[koff + 2][ldr] = vw.z; Ws[koff + 3][ldr] = vw.w;
        __syncthreads();
        #pragma unroll
        for (int kkk = 0; kkk < 8; kkk++) {
            float a[8], b[8];
            *(float4*)(a)     = *(const float4*)&Cs[kkk][ty * 8];
            *(float4*)(a + 4) = *(const float4*)&Cs[kkk][ty * 8 + 4];
            *(float4*)(b)     = *(const float4*)&Ws[kkk][tx * 8];
            *(float4*)(b + 4) = *(const float4*)&Ws[kkk][tx * 8 + 4];
            #pragma unroll
            for (int r = 0; r < 8; r++)
                #pragma unroll
                for (int c = 0; c < 8; c++)
                    acc[r][c] = fmaf(a[r], b[c], acc[r][c]);
        }
        __syncthreads();
    }
    #pragma unroll
    for (int r = 0; r < 8; r++) {
        int k = k0 + ty * 8 + r;
        float s = 0.f;
        #pragma unroll
        for (int c = 0; c < 8; c++) {
            int e = e0 + tx * 8 + c;
            float diff = acc[r][c] + bias[e] - Cb[(size_t)k * DD + e];
            s = fmaf(diff, diff, s);
        }
        #pragma unroll
        for (int o = 1; o < 16; o <<= 1) s += __shfl_xor_sync(0xffffffffu, s, o);
        if (tx == 0) g_spart[blockIdx.y * KK + k] = s;
    }
}

// ------------------------------------------------------------- K3: fp16-acc GEMM 256x256 + top-2
// 512 threads, 16 warps (4x4), warp tile 64x64, 1 CTA/SM.
// 3-buffer circular cp.async pipeline. Per stage: sync -> issue(s+2) -> commit
// (unconditional, keeps group count aligned) -> wait_group(2) -> compute.
// smem: A[3x32K @0) B[3x32K @98304) cbs(1KB)@196608. red (16KB) aliases A0.
#define SMEM_GEMM 197632

__global__ __launch_bounds__(512, 1) void gemm_argmin() {
    extern __shared__ char smraw[];
    uint32_t sb = smem_u32(smraw);
    int tid = threadIdx.x;
    int lane = tid & 31, wid = tid >> 5;
    int wm = wid >> 2, wn = wid & 3;        // warp tile: rows wm*64, cols wn*64
    int row0 = blockIdx.x * MT;
    int ctbase = blockIdx.y * NT;

    uint32_t smA[3], smB[3];
    #pragma unroll
    for (int b = 0; b < 3; b++) {
        smA[b] = sb + b * 32768;
        smB[b] = sb + 98304 + b * 32768;
    }
    float* cbs = (float*)(smraw + 196608);
    float4* red = (float4*)smraw;           // alias: used only after mainloop

    if (tid < NT) cbs[tid] = g_cbsq[ctbase + tid] * CBSCALE;

    const int rA = lane & 15, cA = lane >> 4;
    const int rB = (lane & 7) | ((lane >> 4) << 3);
    const int cB = (lane >> 3) & 1;

    uint32_t acc[4][8][2];                  // f16x2 accumulators (64 regs)
    #pragma unroll
    for (int a = 0; a < 4; a++)
        #pragma unroll
        for (int b = 0; b < 8; b++) { acc[a][b][0] = 0u; acc[a][b][1] = 0u; }

    const int arow = tid >> 1, ah4 = (tid & 1) * 4;

    auto issue = [&](int s, int b) {
        uint32_t x = (uint32_t)(arow & 7);
        {
            const __half* p = g_mh + (size_t)(row0 + arow) * DD + s * KC + ah4 * 8;
            uint32_t base = smA[b] + arow * 128;
            #pragma unroll
            for (int c = 0; c < 4; c++)
                CP16(base + ((((uint32_t)(ah4 + c)) ^ x) << 4), p + 8 * c);
        }
        {
            const __half* p = g_ch + (size_t)(ctbase + arow) * DD + s * KC + ah4 * 8;
            uint32_t base = smB[b] + arow * 128;
            #pragma unroll
            for (int c = 0; c < 4; c++)
                CP16(base + ((((uint32_t)(ah4 + c)) ^ x) << 4), p + 8 * c);
        }
    };

    issue(0, 0); CP_COMMIT();
    issue(1, 1); CP_COMMIT();

    for (int s = 0; s < NSTAGE; s++) {
        const int b = s % 3;
        __syncthreads();                      // all warps done reading buf (s+2)%3 (stage s-1)
        if (s + 2 < NSTAGE) issue(s + 2, (s + 2) % 3);
        CP_COMMIT();                          // unconditional: group count stays aligned
        CP_WAIT2();                           // groups <= s complete

        #pragma unroll
        for (int kk = 0; kk < 4; kk++) {
            uint32_t ah[4][4], bh[8][2];
            #pragma unroll
            for (int mf = 0; mf < 4; mf++) {
                int row = wm * 64 + mf * 16 + rA;
                uint32_t ba = smA[b] + row * 128;
                uint32_t x = (uint32_t)(row & 7);
                LDSM_X4(ah[mf][0], ah[mf][1], ah[mf][2], ah[mf][3],
                        ba + ((((uint32_t)(2 * kk + cA)) ^ x) << 4));
            }
            #pragma unroll
            for (int np = 0; np < 4; np++) {
                int n = wn * 64 + np * 16 + rB;
                uint32_t bb = smB[b] + n * 128;
                uint32_t x = (uint32_t)(n & 7);
                uint32_t t0, t1, t2, t3;
                LDSM_X4(t0, t1, t2, t3, bb + ((((uint32_t)(2 * kk + cB)) ^ x) << 4));
                bh[2 * np][0] = t0; bh[2 * np][1] = t1;
                bh[2 * np + 1][0] = t2; bh[2 * np + 1][1] = t3;
            }
            #pragma unroll
            for (int mf = 0; mf < 4; mf++)
                #pragma unroll
                for (int nf = 0; nf < 8; nf++)
                    mma_f16h(acc[mf][nf], ah[mf], bh[nf]);
        }
    }
    __syncthreads();   // before aliasing smA as red[]

    // ---- epilogue: scores + per-row top-2 ----
    int g = lane >> 2, q = lane & 3;
    #pragma unroll
    for (int mf = 0; mf < 4; mf++) {
        #pragma unroll
        for (int half = 0; half < 2; half++) {
            int rloc = wm * 64 + mf * 16 + half * 8 + g;
            float v1 = 3.4e38f, v2 = 3.4e38f;
            int i1 = 0, i2 = 0;
            #pragma unroll
            for (int nf = 0; nf < 8; nf++) {
                uint32_t pr = acc[mf][nf][half];
                __half2 h2 = *reinterpret_cast<__half2*>(&pr);
                float dv[2] = { __low2float(h2), __high2float(h2) };
                #pragma unroll
                for (int j = 0; j < 2; j++) {
                    int cloc = wn * 64 + nf * 8 + 2 * q + j;
                    float sc = fmaf(-2.0f, dv[j], cbs[cloc]);
                    int code = ctbase + cloc;
                    if (sc < v1) { v2 = v1; i2 = i1; v1 = sc; i1 = code; }
                    else if (sc < v2) { v2 = sc; i2 = code; }
                }
            }
            #pragma unroll
            for (int o = 1; o <= 2; o <<= 1) {
                float w1 = __shfl_xor_sync(0xffffffffu, v1, o);
                int   j1 = __shfl_xor_sync(0xffffffffu, i1, o);
                float w2 = __shfl_xor_sync(0xffffffffu, v2, o);
                int   j2 = __shfl_xor_sync(0xffffffffu, i2, o);
                if (w1 < v1 || (w1 == v1 && j1 < i1)) { v2 = v1; i2 = i1; v1 = w1; i1 = j1; }
                else if (w1 < v2 || (w1 == v2 && j1 < i2)) { v2 = w1; i2 = j1; }
                if (w2 < v1 || (w2 == v1 && j2 < i1)) { v2 = v1; i2 = i1; v1 = w2; i1 = j2; }
                else if (w2 < v2 || (w2 == v2 && j2 < i2)) { v2 = w2; i2 = j2; }
            }
            if (q == 0)
                red[rloc * 4 + wn] =
                    make_float4(v1, __int_as_float(i1), v2, __int_as_float(i2));
        }
    }
    __syncthreads();
    if (tid < MT) {
        float v1 = 3.4e38f, v2 = 3.4e38f;
        int i1 = 0x7fffffff, i2 = 0x7fffffff;
        #pragma unroll
        for (int w = 0; w < 4; w++) {
            float4 p = red[tid * 4 + w];
            float w1 = p.x, w2 = p.z;
            int j1 = __float_as_int(p.y), j2 = __float_as_int(p.w);
            if (w1 < v1 || (w1 == v1 && j1 < i1)) { v2 = v1; i2 = i1; v1 = w1; i1 = j1; }
            else if (w1 < v2 || (w1 == v2 && j1 < i2)) { v2 = w1; i2 = j1; }
            if (w2 < v1 || (w2 == v1 && j2 < i1)) { v2 = v1; i2 = i1; v1 = w2; i1 = j2; }
            else if (w2 < v2 || (w2 == v2 && j2 < i2)) { v2 = w2; i2 = j2; }
        }
        g_part[(size_t)(row0 + tid) * NCTQ + blockIdx.y] =
            make_float4(v1, __int_as_float(i1), v2, __int_as_float(i2));
    }
}

// ------------------------------------------------------------- K4: margin-pruned exact rescore
// Warp per row: 16 candidates (top-2 x 8 tiles); means recomputed from E (fp32 exact).
__global__ __launch_bounds__(256) void combine_kernel(const float* __restrict__ Cb,
                                                      const float4* __restrict__ E4,
                                                      float* __restrict__ out_idx_f,
                                                      float4* __restrict__ out_emb4) {
    int row = blockIdx.x * 8 + (threadIdx.x >> 5);
    int lane = threadIdx.x & 31;

    float v = 3.4e38f;
    int ci = 0x7fffffff;
    if (lane < 16) {
        float4 p = g_part[(size_t)row * NCTQ + (lane & 7)];
        v  = (lane < 8) ? p.x : p.z;
        ci = (lane < 8) ? __float_as_int(p.y) : __float_as_int(p.w);
    }

    float vmin = v;
    #pragma unroll
    for (int o = 16; o; o >>= 1) vmin = fminf(vmin, __shfl_xor_sync(0xffffffffu, vmin, o));

    unsigned mask = __ballot_sync(0xffffffffu, v <= vmin + MARGIN);

    const float4* e0 = E4 + (size_t)(2 * row) * (DD / 4);
    const float4* e1 = E4 + (size_t)(2 * row + 1) * (DD / 4);
    float bv = 3.4e38f;
    int bi = 0x7fffffff;
    while (mask) {
        int src = __ffs(mask) - 1;
        mask &= mask - 1;
        int cand = __shfl_sync(0xffffffffu, ci, src);
        const float4* c4 = (const float4*)&Cb[(size_t)cand * DD];
        float a0 = 0.f, a1 = 0.f, a2 = 0.f, a3 = 0.f;
        #pragma unroll
        for (int j = 0; j < 4; j++) {
            float4 u = e0[lane + 32 * j];
            float4 w = e1[lane + 32 * j];
            float4 cv = c4[lane + 32 * j];
            a0 = fmaf(0.5f * (u.x + w.x), cv.x, a0);
            a1 = fmaf(0.5f * (u.y + w.y), cv.y, a1);
            a2 = fmaf(0.5f * (u.z + w.z), cv.z, a2);
            a3 = fmaf(0.5f * (u.w + w.w), cv.w, a3);
        }
        float dot = (a0 + a1) + (a2 + a3);
        #pragma unroll
        for (int o = 16; o; o >>= 1) dot += __shfl_xor_sync(0xffffffffu, dot, o);
        float sv = fmaf(-2.f, dot, g_cbsq[cand]);
        if (sv < bv || (sv == bv && cand < bi)) { bv = sv; bi = cand; }
    }
    if (lane == 0) {
        g_idx[row] = bi;
        out_idx_f[row] = (float)bi;
    }
    const float4* src4 = (const float4*)&Cb[(size_t)bi * DD];
    float4* dst = out_emb4 + (size_t)row * (DD / 4);
    #pragma unroll
    for (int j = 0; j < 4; j++)
        dst[lane + 32 * j] = src4[lane + 32 * j];
}

// ------------------------------------------------------------- K5a/K5b: two-stage loss
__global__ __launch_bounds__(256) void loss_part_kernel() {
    __shared__ float red[256];
    int n0 = blockIdx.x * (NROWS / 64);
    float s = 0.f;
    for (int n = n0 + threadIdx.x; n < n0 + NROWS / 64; n += 256) {
        int k = g_idx[n];
        s += (g_spart[k] + g_spart[KK + k]) + (g_spart[2 * KK + k] + g_spart[3 * KK + k]);
    }
    red[threadIdx.x] = s;
    __syncthreads();
    for (int st = 128; st > 0; st >>= 1) {
        if (threadIdx.x < st) red[threadIdx.x] += red[threadIdx.x + st];
        __syncthreads();
    }
    if (threadIdx.x == 0) g_lred[blockIdx.x] = red[0];
}
__global__ void loss_fin_kernel(float* __restrict__ out_loss) {
    float s = (threadIdx.x < 64) ? g_lred[threadIdx.x] : 0.f;
    #pragma unroll
    for (int o = 16; o; o >>= 1) s += __shfl_xor_sync(0xffffffffu, s, o);
    __shared__ float w[2];
    if ((threadIdx.x & 31) == 0) w[threadIdx.x >> 5] = s;
    __syncthreads();
    if (threadIdx.x == 0)
        out_loss[0] = (w[0] + w[1]) / (float)((long long)NROWS * DD);
}

// -------------------------------------------------------------
extern "C" void kernel_launch(void* const* d_in, const int* in_sizes, int n_in,
                              void* d_out, int out_size) {
    const float* E    = (const float*)d_in[1];
    const float* Cb   = (const float*)d_in[2];
    const float* W    = (const float*)d_in[3];
    const float* bias = (const float*)d_in[4];

    float* out      = (float*)d_out;
    float* out_idx  = out;
    float* out_emb  = out + NROWS;
    float* out_loss = out + NROWS + NROWS * DD;

    cudaFuncSetAttribute(gemm_argmin, cudaFuncAttributeMaxDynamicSharedMemorySize, SMEM_GEMM);

    means_kernel<<<(NROWS * (DD / 4) + 255) / 256, 256>>>((const float4*)E);
    cbprep_kernel<<<KK / 8, 256>>>((const float4*)Cb);
    prep_gemm<<<dim3(16, 4), 256>>>(Cb, W, bias);
    gemm_argmin<<<dim3(NROWS / MT, NCTQ), 512, SMEM_GEMM>>>();
    combine_kernel<<<NROWS / 8, 256>>>(Cb, (const float4*)E, out_idx, (float4*)out_emb);
    loss_part_kernel<<<64, 256>>>();
    loss_fin_kernel<<<1, 64>>>(out_loss);
}